// round 1
// baseline (speedup 1.0000x reference)
#include <cuda_runtime.h>
#include <math.h>

#define BB 8
#define LL 1000
#define DD 1024
#define HH 16
#define HDIM 64
#define MTOT (BB * LL)   // 8000

// Scratch (allocation-free rule: __device__ globals)
__device__ __align__(16) float g_qkv[(size_t)MTOT * 3 * DD];  // [8000, 3072]
__device__ __align__(16) float g_att[(size_t)MTOT * DD];      // [8000, 1024]

// ---------------------------------------------------------------------------
// SGEMM: C[M,N] = A[M,K] * B[K,N] + bias[N]
// BM=64, BN=128, BK=16, 256 threads, each thread 4x8 outputs.
// Requires M%64==0, N%128==0, K%16==0 (true for all our shapes).
// ---------------------------------------------------------------------------
__global__ __launch_bounds__(256) void sgemm_bias_kernel(
    const float* __restrict__ A, const float* __restrict__ Bm,
    const float* __restrict__ bias, float* __restrict__ C,
    int M, int N, int K)
{
    __shared__ float As[16][64];    // transposed A tile: As[k][m]
    __shared__ float Bs[16][128];   // Bs[k][n]

    const int tid = threadIdx.x;
    const int tx = tid & 15;        // -> N (8 cols each)
    const int ty = tid >> 4;        // -> M (4 rows each)
    const int bm = blockIdx.y * 64;
    const int bn = blockIdx.x * 128;

    const int a_row = tid >> 2;          // 0..63
    const int a_col = (tid & 3) << 2;    // 0,4,8,12
    const int b_row = tid >> 5;          // 0..7
    const int b_col = (tid & 31) << 2;   // 0..124

    const float* Aptr = A + (size_t)(bm + a_row) * K + a_col;
    const float* Bptr = Bm + (size_t)b_row * N + bn + b_col;

    float acc[4][8];
    #pragma unroll
    for (int i = 0; i < 4; i++)
        #pragma unroll
        for (int j = 0; j < 8; j++) acc[i][j] = 0.f;

    for (int k0 = 0; k0 < K; k0 += 16) {
        float4 a4  = *(const float4*)(Aptr + k0);
        float4 b4a = *(const float4*)(Bptr + (size_t)k0 * N);
        float4 b4b = *(const float4*)(Bptr + (size_t)(k0 + 8) * N);

        As[a_col + 0][a_row] = a4.x;
        As[a_col + 1][a_row] = a4.y;
        As[a_col + 2][a_row] = a4.z;
        As[a_col + 3][a_row] = a4.w;
        *(float4*)(&Bs[b_row][b_col])     = b4a;
        *(float4*)(&Bs[b_row + 8][b_col]) = b4b;
        __syncthreads();

        #pragma unroll
        for (int kk = 0; kk < 16; kk++) {
            float4 av  = *(const float4*)(&As[kk][ty * 4]);
            float4 bv0 = *(const float4*)(&Bs[kk][tx * 8]);
            float4 bv1 = *(const float4*)(&Bs[kk][tx * 8 + 4]);
            float a[4]  = {av.x, av.y, av.z, av.w};
            float bb[8] = {bv0.x, bv0.y, bv0.z, bv0.w, bv1.x, bv1.y, bv1.z, bv1.w};
            #pragma unroll
            for (int i = 0; i < 4; i++)
                #pragma unroll
                for (int j = 0; j < 8; j++)
                    acc[i][j] += a[i] * bb[j];
        }
        __syncthreads();
    }

    #pragma unroll
    for (int i = 0; i < 4; i++) {
        int row = bm + ty * 4 + i;
        float* crow = C + (size_t)row * N + bn + tx * 8;
        #pragma unroll
        for (int j = 0; j < 8; j++)
            crow[j] = acc[i][j] + bias[bn + tx * 8 + j];
    }
}

// ---------------------------------------------------------------------------
// Flash attention, causal. One block per (qtile of 64 rows, b*h).
// 256 threads; each thread owns a 4x4 output sub-tile of the 64x64 block.
// smem (dynamic): qs[64][68], kt[64][68] (feature-major), vs[64][68],
//                 ps[64][68], m[64], l[64], alpha[64]
// ---------------------------------------------------------------------------
#define SMS 68   // padded row stride
#define ATTN_SMEM_FLOATS (4 * 64 * SMS + 192)

__global__ __launch_bounds__(256) void attn_kernel(
    const float* __restrict__ qkv, float* __restrict__ att)
{
    extern __shared__ float smem[];
    float* qs   = smem;                  // [row][feat]
    float* kt   = smem + 64 * SMS;       // [feat][key]
    float* vs   = smem + 2 * 64 * SMS;   // [key][feat]
    float* ps   = smem + 3 * 64 * SMS;   // [row][key]
    float* m_sm = smem + 4 * 64 * SMS;
    float* l_sm = m_sm + 64;
    float* a_sm = m_sm + 128;

    const int tid = threadIdx.x;
    const int tx = tid & 15;      // key / feature cols (4 each)
    const int ty = tid >> 4;      // query rows (4 each)
    const int qtile = blockIdx.x;
    const int bh = blockIdx.y;
    const int b = bh >> 4;
    const int h = bh & 15;
    const int q0 = qtile * 64;

    const size_t base = (size_t)b * LL * (3 * DD);
    const float* qptr = qkv + base + h * HDIM;
    const float* kptr = qkv + base + DD + h * HDIM;
    const float* vptr = qkv + base + 2 * DD + h * HDIM;

    // Load Q tile (guard rows >= L)
    #pragma unroll
    for (int rep = 0; rep < 4; rep++) {
        int idx = tid + rep * 256;
        int r = idx >> 4;
        int c4 = (idx & 15) * 4;
        float4 v4 = make_float4(0.f, 0.f, 0.f, 0.f);
        if (q0 + r < LL)
            v4 = *(const float4*)(qptr + (size_t)(q0 + r) * (3 * DD) + c4);
        *(float4*)(qs + r * SMS + c4) = v4;
    }
    if (tid < 64) { m_sm[tid] = -1e30f; l_sm[tid] = 0.f; }

    float o[4][4];
    #pragma unroll
    for (int i = 0; i < 4; i++)
        #pragma unroll
        for (int j = 0; j < 4; j++) o[i][j] = 0.f;

    const float scale = 0.125f;  // 1/sqrt(64)

    for (int j = 0; j <= qtile; j++) {
        __syncthreads();  // prev PV done (and first-iter q/m ready)

        // Load K (transposed into kt) and V tiles
        #pragma unroll
        for (int rep = 0; rep < 4; rep++) {
            int idx = tid + rep * 256;
            int r = idx >> 4;          // key within tile
            int c4 = (idx & 15) * 4;
            int kv = j * 64 + r;
            float4 k4 = make_float4(0.f, 0.f, 0.f, 0.f);
            float4 v4 = make_float4(0.f, 0.f, 0.f, 0.f);
            if (kv < LL) {
                k4 = *(const float4*)(kptr + (size_t)kv * (3 * DD) + c4);
                v4 = *(const float4*)(vptr + (size_t)kv * (3 * DD) + c4);
            }
            kt[(c4 + 0) * SMS + r] = k4.x;
            kt[(c4 + 1) * SMS + r] = k4.y;
            kt[(c4 + 2) * SMS + r] = k4.z;
            kt[(c4 + 3) * SMS + r] = k4.w;
            *(float4*)(vs + r * SMS + c4) = v4;
        }
        __syncthreads();

        // S = Q K^T (4x4 per thread)
        float s[4][4];
        #pragma unroll
        for (int i = 0; i < 4; i++)
            #pragma unroll
            for (int jj = 0; jj < 4; jj++) s[i][jj] = 0.f;

        #pragma unroll 8
        for (int kk = 0; kk < 64; kk++) {
            float a0 = qs[(ty * 4 + 0) * SMS + kk];
            float a1 = qs[(ty * 4 + 1) * SMS + kk];
            float a2 = qs[(ty * 4 + 2) * SMS + kk];
            float a3 = qs[(ty * 4 + 3) * SMS + kk];
            float4 bv = *(const float4*)(kt + kk * SMS + tx * 4);
            s[0][0] += a0 * bv.x; s[0][1] += a0 * bv.y; s[0][2] += a0 * bv.z; s[0][3] += a0 * bv.w;
            s[1][0] += a1 * bv.x; s[1][1] += a1 * bv.y; s[1][2] += a1 * bv.z; s[1][3] += a1 * bv.w;
            s[2][0] += a2 * bv.x; s[2][1] += a2 * bv.y; s[2][2] += a2 * bv.z; s[2][3] += a2 * bv.w;
            s[3][0] += a3 * bv.x; s[3][1] += a3 * bv.y; s[3][2] += a3 * bv.z; s[3][3] += a3 * bv.w;
        }

        // Scale + causal mask (only diagonal tile needs masking), write to ps
        const bool masked = (j == qtile);
        #pragma unroll
        for (int i = 0; i < 4; i++) {
            int rg = q0 + ty * 4 + i;
            #pragma unroll
            for (int jj = 0; jj < 4; jj++) {
                int cg = j * 64 + tx * 4 + jj;
                float val = s[i][jj] * scale;
                if (masked && (cg > rg || cg >= LL)) val = -1e30f;
                ps[(ty * 4 + i) * SMS + tx * 4 + jj] = val;
            }
        }
        __syncthreads();

        // Online softmax per row (64 threads, one row each)
        if (tid < 64) {
            float* prow = ps + tid * SMS;
            float mo = m_sm[tid];
            float mx = mo;
            #pragma unroll 16
            for (int c = 0; c < 64; c++) mx = fmaxf(mx, prow[c]);
            float al = __expf(mo - mx);
            float sum = 0.f;
            #pragma unroll 16
            for (int c = 0; c < 64; c++) {
                float p = __expf(prow[c] - mx);
                prow[c] = p;
                sum += p;
            }
            m_sm[tid] = mx;
            l_sm[tid] = l_sm[tid] * al + sum;
            a_sm[tid] = al;
        }
        __syncthreads();

        // Rescale O and accumulate P*V
        float alr[4];
        #pragma unroll
        for (int i = 0; i < 4; i++) alr[i] = a_sm[ty * 4 + i];
        #pragma unroll
        for (int i = 0; i < 4; i++)
            #pragma unroll
            for (int jj = 0; jj < 4; jj++) o[i][jj] *= alr[i];

        #pragma unroll 8
        for (int kk = 0; kk < 64; kk++) {
            float p0 = ps[(ty * 4 + 0) * SMS + kk];
            float p1 = ps[(ty * 4 + 1) * SMS + kk];
            float p2 = ps[(ty * 4 + 2) * SMS + kk];
            float p3 = ps[(ty * 4 + 3) * SMS + kk];
            float4 vv = *(const float4*)(vs + kk * SMS + tx * 4);
            o[0][0] += p0 * vv.x; o[0][1] += p0 * vv.y; o[0][2] += p0 * vv.z; o[0][3] += p0 * vv.w;
            o[1][0] += p1 * vv.x; o[1][1] += p1 * vv.y; o[1][2] += p1 * vv.z; o[1][3] += p1 * vv.w;
            o[2][0] += p2 * vv.x; o[2][1] += p2 * vv.y; o[2][2] += p2 * vv.z; o[2][3] += p2 * vv.w;
            o[3][0] += p3 * vv.x; o[3][1] += p3 * vv.y; o[3][2] += p3 * vv.z; o[3][3] += p3 * vv.w;
        }
    }
    __syncthreads();

    // Normalize and store
    #pragma unroll
    for (int i = 0; i < 4; i++) {
        int r = q0 + ty * 4 + i;
        if (r < LL) {
            float inv = 1.0f / l_sm[ty * 4 + i];
            float4 w = make_float4(o[i][0] * inv, o[i][1] * inv,
                                   o[i][2] * inv, o[i][3] * inv);
            *(float4*)(att + (size_t)(b * LL + r) * DD + h * HDIM + tx * 4) = w;
        }
    }
}

// ---------------------------------------------------------------------------
extern "C" void kernel_launch(void* const* d_in, const int* in_sizes, int n_in,
                              void* d_out, int out_size)
{
    const float* x    = (const float*)d_in[0];  // [8,1000,1024]
    const float* Wqkv = (const float*)d_in[1];  // [1024,3072]
    const float* bqkv = (const float*)d_in[2];  // [3072]
    const float* Wo   = (const float*)d_in[3];  // [1024,1024]
    const float* bo   = (const float*)d_in[4];  // [1024]
    float* out = (float*)d_out;                 // [8,1000,1024]

    float* qkv; cudaGetSymbolAddress((void**)&qkv, g_qkv);
    float* att; cudaGetSymbolAddress((void**)&att, g_att);

    const int attn_smem = ATTN_SMEM_FLOATS * (int)sizeof(float);  // 70400 B
    cudaFuncSetAttribute(attn_kernel,
                         cudaFuncAttributeMaxDynamicSharedMemorySize, attn_smem);

    // 1) QKV projection: [8000,3072]
    sgemm_bias_kernel<<<dim3(3 * DD / 128, MTOT / 64), 256>>>(
        x, Wqkv, bqkv, qkv, MTOT, 3 * DD, DD);

    // 2) Causal flash attention -> g_att [8000,1024]
    attn_kernel<<<dim3(16, BB * HH), 256, attn_smem>>>(qkv, att);

    // 3) Output projection: [8000,1024]
    sgemm_bias_kernel<<<dim3(DD / 128, MTOT / 64), 256>>>(
        att, Wo, bo, out, MTOT, DD, DD);
}

// round 2
// speedup vs baseline: 2.6462x; 2.6462x over previous
#include <cuda_runtime.h>
#include <math.h>

#define BB 8
#define LL 1000
#define DD 1024
#define HH 16
#define HDIM 64
#define MTOT (BB * LL)   // 8000

// Scratch (allocation-free rule: __device__ globals)
__device__ __align__(16) float g_qkv[(size_t)MTOT * 3 * DD];  // [8000, 3072]
__device__ __align__(16) float g_att[(size_t)MTOT * DD];      // [8000, 1024]

// ---------------------------------------------------------------------------
// TF32 tensor-core GEMM: C[M,N] = A[M,K] * B[K,N] + bias[N]
// Block tile 128x128x32, 256 threads (8 warps, each 64x32), double-buffered
// cp.async. Requires N%128==0, K%32==0; M guarded.
// ---------------------------------------------------------------------------
#define TBM 128
#define TBN 128
#define TBK 32
#define ASTRIDE 36    // 32 + 4 pad  -> conflict-free A fragment loads
#define BSTRIDE 136   // 128 + 8 pad -> conflict-free B fragment loads
#define ASZ (TBM * ASTRIDE)
#define BSZ (TBK * BSTRIDE)

__device__ __forceinline__ unsigned f2tf32(float f) {
    unsigned u;
    asm("cvt.rna.tf32.f32 %0, %1;" : "=r"(u) : "f"(f));
    return u;
}

__device__ __forceinline__ void mma_tf32(float* c, const unsigned* a, const unsigned* b) {
    asm volatile(
        "mma.sync.aligned.m16n8k8.row.col.f32.tf32.tf32.f32 "
        "{%0,%1,%2,%3},{%4,%5,%6,%7},{%8,%9},{%0,%1,%2,%3};"
        : "+f"(c[0]), "+f"(c[1]), "+f"(c[2]), "+f"(c[3])
        : "r"(a[0]), "r"(a[1]), "r"(a[2]), "r"(a[3]), "r"(b[0]), "r"(b[1]));
}

__device__ __forceinline__ void cp_async16(float* smem_dst, const float* gsrc, bool pred) {
    unsigned saddr = (unsigned)__cvta_generic_to_shared(smem_dst);
    int sz = pred ? 16 : 0;
    asm volatile("cp.async.cg.shared.global [%0], [%1], 16, %2;\n"
                 :: "r"(saddr), "l"(gsrc), "r"(sz));
}
__device__ __forceinline__ void cp_commit() { asm volatile("cp.async.commit_group;\n" ::); }
template <int N>
__device__ __forceinline__ void cp_wait() { asm volatile("cp.async.wait_group %0;\n" :: "n"(N)); }

__global__ __launch_bounds__(256) void gemm_tf32_bias_kernel(
    const float* __restrict__ A, const float* __restrict__ Bm,
    const float* __restrict__ bias, float* __restrict__ C,
    int M, int N, int K)
{
    extern __shared__ float smem[];
    float* As = smem;                 // [2][TBM][ASTRIDE]
    float* Bs = smem + 2 * ASZ;       // [2][TBK][BSTRIDE]

    const int tid = threadIdx.x;
    const int lane = tid & 31;
    const int warp = tid >> 5;
    const int wm = (warp & 1) * 64;   // warp row offset in block tile
    const int wn = (warp >> 1) * 32;  // warp col offset
    const int bm = blockIdx.y * TBM;
    const int bn = blockIdx.x * TBN;

    // global->smem mapping (per 16B chunk)
    const int a_row = tid >> 1;             // 2 chunks per row? no: A row has 8 chunks
    // A: 1024 chunks/tile, 4 per thread. chunk = tid + i*256: row = chunk>>3, k4 = chunk&7
    // B: 1024 chunks/tile, 4 per thread. chunk = tid + i*256: row = chunk>>5, n4 = chunk&31
    (void)a_row;

    float acc[4][4][4];
    #pragma unroll
    for (int i = 0; i < 4; i++)
        #pragma unroll
        for (int j = 0; j < 4; j++)
            #pragma unroll
            for (int r = 0; r < 4; r++) acc[i][j][r] = 0.f;

    const int nT = K / TBK;

    // prefetch tile 0
    {
        #pragma unroll
        for (int i = 0; i < 4; i++) {
            int chunk = tid + i * 256;
            int row = chunk >> 3, k4 = chunk & 7;
            bool ok = (bm + row) < M;
            cp_async16(As + row * ASTRIDE + k4 * 4,
                       A + (size_t)(bm + row) * K + k4 * 4, ok);
        }
        #pragma unroll
        for (int i = 0; i < 4; i++) {
            int chunk = tid + i * 256;
            int row = chunk >> 5, n4 = chunk & 31;
            cp_async16(Bs + row * BSTRIDE + n4 * 4,
                       Bm + (size_t)row * N + bn + n4 * 4, true);
        }
        cp_commit();
    }

    for (int t = 0; t < nT; t++) {
        int cur = t & 1;
        int nxt = cur ^ 1;
        if (t + 1 < nT) {
            int k0 = (t + 1) * TBK;
            #pragma unroll
            for (int i = 0; i < 4; i++) {
                int chunk = tid + i * 256;
                int row = chunk >> 3, k4 = chunk & 7;
                bool ok = (bm + row) < M;
                cp_async16(As + nxt * ASZ + row * ASTRIDE + k4 * 4,
                           A + (size_t)(bm + row) * K + k0 + k4 * 4, ok);
            }
            #pragma unroll
            for (int i = 0; i < 4; i++) {
                int chunk = tid + i * 256;
                int row = chunk >> 5, n4 = chunk & 31;
                cp_async16(Bs + nxt * BSZ + row * BSTRIDE + n4 * 4,
                           Bm + (size_t)(k0 + row) * N + bn + n4 * 4, true);
            }
            cp_commit();
            cp_wait<1>();   // tile t resident
        } else {
            cp_wait<0>();
        }
        __syncthreads();

        const float* Ab = As + cur * ASZ;
        const float* Bb = Bs + cur * BSZ;

        #pragma unroll
        for (int ks = 0; ks < 4; ks++) {
            int k = ks * 8;
            unsigned afr[4][4];
            unsigned bfr[4][2];
            #pragma unroll
            for (int mt = 0; mt < 4; mt++) {
                int r0 = wm + mt * 16 + (lane >> 2);
                int c0 = k + (lane & 3);
                afr[mt][0] = f2tf32(Ab[(r0)     * ASTRIDE + c0]);
                afr[mt][1] = f2tf32(Ab[(r0 + 8) * ASTRIDE + c0]);
                afr[mt][2] = f2tf32(Ab[(r0)     * ASTRIDE + c0 + 4]);
                afr[mt][3] = f2tf32(Ab[(r0 + 8) * ASTRIDE + c0 + 4]);
            }
            #pragma unroll
            for (int nt = 0; nt < 4; nt++) {
                int col = wn + nt * 8 + (lane >> 2);
                int r0 = k + (lane & 3);
                bfr[nt][0] = f2tf32(Bb[(r0)     * BSTRIDE + col]);
                bfr[nt][1] = f2tf32(Bb[(r0 + 4) * BSTRIDE + col]);
            }
            #pragma unroll
            for (int mt = 0; mt < 4; mt++)
                #pragma unroll
                for (int nt = 0; nt < 4; nt++)
                    mma_tf32(acc[mt][nt], afr[mt], bfr[nt]);
        }
        __syncthreads();
    }

    // epilogue: bias add + guarded store (float2 per c-pair)
    #pragma unroll
    for (int mt = 0; mt < 4; mt++) {
        int r_lo = bm + wm + mt * 16 + (lane >> 2);
        int r_hi = r_lo + 8;
        #pragma unroll
        for (int nt = 0; nt < 4; nt++) {
            int col = bn + wn + nt * 8 + (lane & 3) * 2;
            float b0 = bias[col], b1 = bias[col + 1];
            if (r_lo < M) {
                float2 w = make_float2(acc[mt][nt][0] + b0, acc[mt][nt][1] + b1);
                *(float2*)(C + (size_t)r_lo * N + col) = w;
            }
            if (r_hi < M) {
                float2 w = make_float2(acc[mt][nt][2] + b0, acc[mt][nt][3] + b1);
                *(float2*)(C + (size_t)r_hi * N + col) = w;
            }
        }
    }
}

// ---------------------------------------------------------------------------
// Flash attention, causal. One block per (qtile of 64 rows, b*h).
// 256 threads; each thread owns a 4x4 output sub-tile of the 64x64 block.
// ---------------------------------------------------------------------------
#define SMS 68   // padded row stride
#define ATTN_SMEM_FLOATS (4 * 64 * SMS + 192)

__global__ __launch_bounds__(256) void attn_kernel(
    const float* __restrict__ qkv, float* __restrict__ att)
{
    extern __shared__ float smem[];
    float* qs   = smem;                  // [row][feat]
    float* kt   = smem + 64 * SMS;       // [feat][key]
    float* vs   = smem + 2 * 64 * SMS;   // [key][feat]
    float* ps   = smem + 3 * 64 * SMS;   // [row][key]
    float* m_sm = smem + 4 * 64 * SMS;
    float* l_sm = m_sm + 64;
    float* a_sm = m_sm + 128;

    const int tid = threadIdx.x;
    const int tx = tid & 15;
    const int ty = tid >> 4;
    const int qtile = blockIdx.x;
    const int bh = blockIdx.y;
    const int b = bh >> 4;
    const int h = bh & 15;
    const int q0 = qtile * 64;

    const size_t base = (size_t)b * LL * (3 * DD);
    const float* qptr = qkv + base + h * HDIM;
    const float* kptr = qkv + base + DD + h * HDIM;
    const float* vptr = qkv + base + 2 * DD + h * HDIM;

    #pragma unroll
    for (int rep = 0; rep < 4; rep++) {
        int idx = tid + rep * 256;
        int r = idx >> 4;
        int c4 = (idx & 15) * 4;
        float4 v4 = make_float4(0.f, 0.f, 0.f, 0.f);
        if (q0 + r < LL)
            v4 = *(const float4*)(qptr + (size_t)(q0 + r) * (3 * DD) + c4);
        *(float4*)(qs + r * SMS + c4) = v4;
    }
    if (tid < 64) { m_sm[tid] = -1e30f; l_sm[tid] = 0.f; }

    float o[4][4];
    #pragma unroll
    for (int i = 0; i < 4; i++)
        #pragma unroll
        for (int j = 0; j < 4; j++) o[i][j] = 0.f;

    const float scale = 0.125f;

    for (int j = 0; j <= qtile; j++) {
        __syncthreads();

        #pragma unroll
        for (int rep = 0; rep < 4; rep++) {
            int idx = tid + rep * 256;
            int r = idx >> 4;
            int c4 = (idx & 15) * 4;
            int kv = j * 64 + r;
            float4 k4 = make_float4(0.f, 0.f, 0.f, 0.f);
            float4 v4 = make_float4(0.f, 0.f, 0.f, 0.f);
            if (kv < LL) {
                k4 = *(const float4*)(kptr + (size_t)kv * (3 * DD) + c4);
                v4 = *(const float4*)(vptr + (size_t)kv * (3 * DD) + c4);
            }
            kt[(c4 + 0) * SMS + r] = k4.x;
            kt[(c4 + 1) * SMS + r] = k4.y;
            kt[(c4 + 2) * SMS + r] = k4.z;
            kt[(c4 + 3) * SMS + r] = k4.w;
            *(float4*)(vs + r * SMS + c4) = v4;
        }
        __syncthreads();

        float s[4][4];
        #pragma unroll
        for (int i = 0; i < 4; i++)
            #pragma unroll
            for (int jj = 0; jj < 4; jj++) s[i][jj] = 0.f;

        #pragma unroll 8
        for (int kk = 0; kk < 64; kk++) {
            float a0 = qs[(ty * 4 + 0) * SMS + kk];
            float a1 = qs[(ty * 4 + 1) * SMS + kk];
            float a2 = qs[(ty * 4 + 2) * SMS + kk];
            float a3 = qs[(ty * 4 + 3) * SMS + kk];
            float4 bv = *(const float4*)(kt + kk * SMS + tx * 4);
            s[0][0] += a0 * bv.x; s[0][1] += a0 * bv.y; s[0][2] += a0 * bv.z; s[0][3] += a0 * bv.w;
            s[1][0] += a1 * bv.x; s[1][1] += a1 * bv.y; s[1][2] += a1 * bv.z; s[1][3] += a1 * bv.w;
            s[2][0] += a2 * bv.x; s[2][1] += a2 * bv.y; s[2][2] += a2 * bv.z; s[2][3] += a2 * bv.w;
            s[3][0] += a3 * bv.x; s[3][1] += a3 * bv.y; s[3][2] += a3 * bv.z; s[3][3] += a3 * bv.w;
        }

        const bool masked = (j == qtile);
        #pragma unroll
        for (int i = 0; i < 4; i++) {
            int rg = q0 + ty * 4 + i;
            #pragma unroll
            for (int jj = 0; jj < 4; jj++) {
                int cg = j * 64 + tx * 4 + jj;
                float val = s[i][jj] * scale;
                if (masked && (cg > rg || cg >= LL)) val = -1e30f;
                ps[(ty * 4 + i) * SMS + tx * 4 + jj] = val;
            }
        }
        __syncthreads();

        if (tid < 64) {
            float* prow = ps + tid * SMS;
            float mo = m_sm[tid];
            float mx = mo;
            #pragma unroll 16
            for (int c = 0; c < 64; c++) mx = fmaxf(mx, prow[c]);
            float al = __expf(mo - mx);
            float sum = 0.f;
            #pragma unroll 16
            for (int c = 0; c < 64; c++) {
                float p = __expf(prow[c] - mx);
                prow[c] = p;
                sum += p;
            }
            m_sm[tid] = mx;
            l_sm[tid] = l_sm[tid] * al + sum;
            a_sm[tid] = al;
        }
        __syncthreads();

        float alr[4];
        #pragma unroll
        for (int i = 0; i < 4; i++) alr[i] = a_sm[ty * 4 + i];
        #pragma unroll
        for (int i = 0; i < 4; i++)
            #pragma unroll
            for (int jj = 0; jj < 4; jj++) o[i][jj] *= alr[i];

        #pragma unroll 8
        for (int kk = 0; kk < 64; kk++) {
            float p0 = ps[(ty * 4 + 0) * SMS + kk];
            float p1 = ps[(ty * 4 + 1) * SMS + kk];
            float p2 = ps[(ty * 4 + 2) * SMS + kk];
            float p3 = ps[(ty * 4 + 3) * SMS + kk];
            float4 vv = *(const float4*)(vs + kk * SMS + tx * 4);
            o[0][0] += p0 * vv.x; o[0][1] += p0 * vv.y; o[0][2] += p0 * vv.z; o[0][3] += p0 * vv.w;
            o[1][0] += p1 * vv.x; o[1][1] += p1 * vv.y; o[1][2] += p1 * vv.z; o[1][3] += p1 * vv.w;
            o[2][0] += p2 * vv.x; o[2][1] += p2 * vv.y; o[2][2] += p2 * vv.z; o[2][3] += p2 * vv.w;
            o[3][0] += p3 * vv.x; o[3][1] += p3 * vv.y; o[3][2] += p3 * vv.z; o[3][3] += p3 * vv.w;
        }
    }
    __syncthreads();

    #pragma unroll
    for (int i = 0; i < 4; i++) {
        int r = q0 + ty * 4 + i;
        if (r < LL) {
            float inv = 1.0f / l_sm[ty * 4 + i];
            float4 w = make_float4(o[i][0] * inv, o[i][1] * inv,
                                   o[i][2] * inv, o[i][3] * inv);
            *(float4*)(att + (size_t)(b * LL + r) * DD + h * HDIM + tx * 4) = w;
        }
    }
}

// ---------------------------------------------------------------------------
extern "C" void kernel_launch(void* const* d_in, const int* in_sizes, int n_in,
                              void* d_out, int out_size)
{
    const float* x    = (const float*)d_in[0];  // [8,1000,1024]
    const float* Wqkv = (const float*)d_in[1];  // [1024,3072]
    const float* bqkv = (const float*)d_in[2];  // [3072]
    const float* Wo   = (const float*)d_in[3];  // [1024,1024]
    const float* bo   = (const float*)d_in[4];  // [1024]
    float* out = (float*)d_out;                 // [8,1000,1024]

    float* qkv; cudaGetSymbolAddress((void**)&qkv, g_qkv);
    float* att; cudaGetSymbolAddress((void**)&att, g_att);

    const int gemm_smem = 2 * (ASZ + BSZ) * (int)sizeof(float);  // 71680 B
    cudaFuncSetAttribute(gemm_tf32_bias_kernel,
                         cudaFuncAttributeMaxDynamicSharedMemorySize, gemm_smem);
    const int attn_smem = ATTN_SMEM_FLOATS * (int)sizeof(float);  // 70400 B
    cudaFuncSetAttribute(attn_kernel,
                         cudaFuncAttributeMaxDynamicSharedMemorySize, attn_smem);

    const int gridM = (MTOT + TBM - 1) / TBM;  // 63

    // 1) QKV projection: [8000,3072]
    gemm_tf32_bias_kernel<<<dim3(3 * DD / TBN, gridM), 256, gemm_smem>>>(
        x, Wqkv, bqkv, qkv, MTOT, 3 * DD, DD);

    // 2) Causal flash attention -> g_att [8000,1024]
    attn_kernel<<<dim3(16, BB * HH), 256, attn_smem>>>(qkv, att);

    // 3) Output projection: [8000,1024]
    gemm_tf32_bias_kernel<<<dim3(DD / TBN, gridM), 256, gemm_smem>>>(
        att, Wo, bo, out, MTOT, DD, DD);
}

// round 3
// speedup vs baseline: 4.5900x; 1.7346x over previous
#include <cuda_runtime.h>
#include <math.h>

#define BB 8
#define LL 1000
#define DD 1024
#define HH 16
#define HDIM 64
#define MTOT (BB * LL)   // 8000

__device__ __align__(16) float g_qkv[(size_t)MTOT * 3 * DD];  // [8000, 3072]
__device__ __align__(16) float g_att[(size_t)MTOT * DD];      // [8000, 1024]

// ---------------------------------------------------------------------------
// Common MMA helpers (m16n8k8 TF32)
// ---------------------------------------------------------------------------
__device__ __forceinline__ unsigned f2tf32(float f) {
    unsigned u;
    asm("cvt.rna.tf32.f32 %0, %1;" : "=r"(u) : "f"(f));
    return u;
}

__device__ __forceinline__ void mma_tf32(float* c, const unsigned* a, const unsigned* b) {
    asm volatile(
        "mma.sync.aligned.m16n8k8.row.col.f32.tf32.tf32.f32 "
        "{%0,%1,%2,%3},{%4,%5,%6,%7},{%8,%9},{%0,%1,%2,%3};"
        : "+f"(c[0]), "+f"(c[1]), "+f"(c[2]), "+f"(c[3])
        : "r"(a[0]), "r"(a[1]), "r"(a[2]), "r"(a[3]), "r"(b[0]), "r"(b[1]));
}

__device__ __forceinline__ void cp_async16(float* smem_dst, const float* gsrc, bool pred) {
    unsigned saddr = (unsigned)__cvta_generic_to_shared(smem_dst);
    int sz = pred ? 16 : 0;
    asm volatile("cp.async.cg.shared.global [%0], [%1], 16, %2;\n"
                 :: "r"(saddr), "l"(gsrc), "r"(sz));
}
__device__ __forceinline__ void cp_commit() { asm volatile("cp.async.commit_group;\n" ::); }
template <int N>
__device__ __forceinline__ void cp_wait() { asm volatile("cp.async.wait_group %0;\n" :: "n"(N)); }

// ---------------------------------------------------------------------------
// TF32 tensor-core GEMM: C = A*B + bias. 128x128x32 tile, 256 thr, 8 warps.
// ---------------------------------------------------------------------------
#define TBM 128
#define TBN 128
#define TBK 32
#define ASTRIDE 36
#define BSTRIDE 136
#define ASZ (TBM * ASTRIDE)
#define BSZ (TBK * BSTRIDE)

__global__ __launch_bounds__(256, 2) void gemm_tf32_bias_kernel(
    const float* __restrict__ A, const float* __restrict__ Bm,
    const float* __restrict__ bias, float* __restrict__ C,
    int M, int N, int K)
{
    extern __shared__ float smem[];
    float* As = smem;
    float* Bs = smem + 2 * ASZ;

    const int tid = threadIdx.x;
    const int lane = tid & 31;
    const int warp = tid >> 5;
    const int wm = (warp & 1) * 64;
    const int wn = (warp >> 1) * 32;
    const int bm = blockIdx.y * TBM;
    const int bn = blockIdx.x * TBN;

    float acc[4][4][4];
    #pragma unroll
    for (int i = 0; i < 4; i++)
        #pragma unroll
        for (int j = 0; j < 4; j++)
            #pragma unroll
            for (int r = 0; r < 4; r++) acc[i][j][r] = 0.f;

    const int nT = K / TBK;

    {
        #pragma unroll
        for (int i = 0; i < 4; i++) {
            int chunk = tid + i * 256;
            int row = chunk >> 3, k4 = chunk & 7;
            bool ok = (bm + row) < M;
            cp_async16(As + row * ASTRIDE + k4 * 4,
                       A + (size_t)(bm + row) * K + k4 * 4, ok);
        }
        #pragma unroll
        for (int i = 0; i < 4; i++) {
            int chunk = tid + i * 256;
            int row = chunk >> 5, n4 = chunk & 31;
            cp_async16(Bs + row * BSTRIDE + n4 * 4,
                       Bm + (size_t)row * N + bn + n4 * 4, true);
        }
        cp_commit();
    }

    for (int t = 0; t < nT; t++) {
        int cur = t & 1;
        int nxt = cur ^ 1;
        if (t + 1 < nT) {
            int k0 = (t + 1) * TBK;
            #pragma unroll
            for (int i = 0; i < 4; i++) {
                int chunk = tid + i * 256;
                int row = chunk >> 3, k4 = chunk & 7;
                bool ok = (bm + row) < M;
                cp_async16(As + nxt * ASZ + row * ASTRIDE + k4 * 4,
                           A + (size_t)(bm + row) * K + k0 + k4 * 4, ok);
            }
            #pragma unroll
            for (int i = 0; i < 4; i++) {
                int chunk = tid + i * 256;
                int row = chunk >> 5, n4 = chunk & 31;
                cp_async16(Bs + nxt * BSZ + row * BSTRIDE + n4 * 4,
                           Bm + (size_t)(k0 + row) * N + bn + n4 * 4, true);
            }
            cp_commit();
            cp_wait<1>();
        } else {
            cp_wait<0>();
        }
        __syncthreads();

        const float* Ab = As + cur * ASZ;
        const float* Bb = Bs + cur * BSZ;

        #pragma unroll
        for (int ks = 0; ks < 4; ks++) {
            int k = ks * 8;
            unsigned afr[4][4];
            unsigned bfr[4][2];
            #pragma unroll
            for (int mt = 0; mt < 4; mt++) {
                int r0 = wm + mt * 16 + (lane >> 2);
                int c0 = k + (lane & 3);
                afr[mt][0] = f2tf32(Ab[(r0)     * ASTRIDE + c0]);
                afr[mt][1] = f2tf32(Ab[(r0 + 8) * ASTRIDE + c0]);
                afr[mt][2] = f2tf32(Ab[(r0)     * ASTRIDE + c0 + 4]);
                afr[mt][3] = f2tf32(Ab[(r0 + 8) * ASTRIDE + c0 + 4]);
            }
            #pragma unroll
            for (int nt = 0; nt < 4; nt++) {
                int col = wn + nt * 8 + (lane >> 2);
                int r0 = k + (lane & 3);
                bfr[nt][0] = f2tf32(Bb[(r0)     * BSTRIDE + col]);
                bfr[nt][1] = f2tf32(Bb[(r0 + 4) * BSTRIDE + col]);
            }
            #pragma unroll
            for (int mt = 0; mt < 4; mt++)
                #pragma unroll
                for (int nt = 0; nt < 4; nt++)
                    mma_tf32(acc[mt][nt], afr[mt], bfr[nt]);
        }
        __syncthreads();
    }

    #pragma unroll
    for (int mt = 0; mt < 4; mt++) {
        int r_lo = bm + wm + mt * 16 + (lane >> 2);
        int r_hi = r_lo + 8;
        #pragma unroll
        for (int nt = 0; nt < 4; nt++) {
            int col = bn + wn + nt * 8 + (lane & 3) * 2;
            float b0 = bias[col], b1 = bias[col + 1];
            if (r_lo < M) {
                float2 w = make_float2(acc[mt][nt][0] + b0, acc[mt][nt][1] + b1);
                *(float2*)(C + (size_t)r_lo * N + col) = w;
            }
            if (r_hi < M) {
                float2 w = make_float2(acc[mt][nt][2] + b0, acc[mt][nt][3] + b1);
                *(float2*)(C + (size_t)r_hi * N + col) = w;
            }
        }
    }
}

// ---------------------------------------------------------------------------
// Tensor-core flash attention (causal), TF32 m16n8k8.
// Block: 128 threads = 4 warps; each warp owns 16 Q-rows of a 64-row tile.
// Q frags in registers; K/V double-buffered cp.async; P staged via smem.
// ---------------------------------------------------------------------------
#define AT_SMS 68
#define AT_TILE (64 * AT_SMS)                 // floats per 64x64 tile buffer
#define ATTN_SMEM_BYTES ((4 * AT_TILE + AT_TILE) * 4)  // 2xK + 2xV + P = 87040

__device__ __forceinline__ void attn_issue_kv(
    float* kdst, float* vdst, const float* kptr, const float* vptr,
    int j, int tid)
{
    #pragma unroll
    for (int i = 0; i < 8; i++) {
        int chunk = tid + i * 128;
        int r = chunk >> 4;
        int c = (chunk & 15) * 4;
        int kv = j * 64 + r;
        if (kv >= LL) kv = LL - 1;   // clamped; masked in S
        cp_async16(kdst + r * AT_SMS + c, kptr + (size_t)kv * (3 * DD) + c, true);
        cp_async16(vdst + r * AT_SMS + c, vptr + (size_t)kv * (3 * DD) + c, true);
    }
}

__global__ __launch_bounds__(128) void attn_mma_kernel(
    const float* __restrict__ qkv, float* __restrict__ att)
{
    extern __shared__ float smem[];
    float* ks = smem;                   // [2][64][AT_SMS]
    float* vs = smem + 2 * AT_TILE;     // [2][64][AT_SMS]
    float* ps = smem + 4 * AT_TILE;     // [64][AT_SMS]  (Q staging, then P)

    const int tid = threadIdx.x;
    const int lane = tid & 31;
    const int warp = tid >> 5;
    const int qtile = 15 - blockIdx.x;   // big tiles first
    const int bh = blockIdx.y;
    const int b = bh >> 4;
    const int h = bh & 15;
    const int q0 = qtile * 64;

    const size_t base = (size_t)b * LL * (3 * DD);
    const float* qptr = qkv + base + h * HDIM;
    const float* kptr = qkv + base + DD + h * HDIM;
    const float* vptr = qkv + base + 2 * DD + h * HDIM;

    // Stage Q tile into ps (coalesced), rows clamped
    #pragma unroll
    for (int i = 0; i < 8; i++) {
        int chunk = tid + i * 128;
        int r = chunk >> 4;
        int c = (chunk & 15) * 4;
        int qr = q0 + r;
        if (qr >= LL) qr = LL - 1;
        float4 v4 = *(const float4*)(qptr + (size_t)qr * (3 * DD) + c);
        *(float4*)(ps + r * AT_SMS + c) = v4;
    }
    __syncthreads();

    // Q fragments (scaled by 1/8), held for the whole loop
    const int r0 = warp * 16 + (lane >> 2);
    unsigned qa[8][4];
    #pragma unroll
    for (int kc = 0; kc < 8; kc++) {
        int c0 = kc * 8 + (lane & 3);
        qa[kc][0] = f2tf32(0.125f * ps[(r0)     * AT_SMS + c0]);
        qa[kc][1] = f2tf32(0.125f * ps[(r0 + 8) * AT_SMS + c0]);
        qa[kc][2] = f2tf32(0.125f * ps[(r0)     * AT_SMS + c0 + 4]);
        qa[kc][3] = f2tf32(0.125f * ps[(r0 + 8) * AT_SMS + c0 + 4]);
    }

    // Prologue: K/V tile 0
    attn_issue_kv(ks, vs, kptr, vptr, 0, tid);
    cp_commit();

    float o[8][4];
    #pragma unroll
    for (int nt = 0; nt < 8; nt++)
        #pragma unroll
        for (int r = 0; r < 4; r++) o[nt][r] = 0.f;
    float m0 = -1e30f, m1 = -1e30f, l0 = 0.f, l1 = 0.f;

    for (int j = 0; j <= qtile; j++) {
        int cur = j & 1;
        int nxt = cur ^ 1;
        cp_wait<0>();
        __syncthreads();   // data visible; prior reads of nxt buffers done

        if (j < qtile) {
            attn_issue_kv(ks + nxt * AT_TILE, vs + nxt * AT_TILE,
                          kptr, vptr, j + 1, tid);
            cp_commit();
        }

        const float* K = ks + cur * AT_TILE;
        const float* V = vs + cur * AT_TILE;

        // S = (Q/8) K^T  [16 x 64 per warp]
        float s[8][4];
        #pragma unroll
        for (int nt = 0; nt < 8; nt++)
            #pragma unroll
            for (int r = 0; r < 4; r++) s[nt][r] = 0.f;

        #pragma unroll
        for (int kc = 0; kc < 8; kc++) {
            #pragma unroll
            for (int nt = 0; nt < 8; nt++) {
                int n0 = nt * 8 + (lane >> 2);
                unsigned bf[2];
                bf[0] = f2tf32(K[n0 * AT_SMS + kc * 8 + (lane & 3)]);
                bf[1] = f2tf32(K[n0 * AT_SMS + kc * 8 + (lane & 3) + 4]);
                mma_tf32(s[nt], qa[kc], bf);
            }
        }

        // Causal mask (diagonal tile only; also kv >= L)
        if (j == qtile) {
            int ri0 = r0;           // row within tile
            int ri1 = r0 + 8;
            #pragma unroll
            for (int nt = 0; nt < 8; nt++) {
                int c0 = nt * 8 + 2 * (lane & 3);
                int c1 = c0 + 1;
                bool bad0 = (c0 > ri0) || (q0 + c0 >= LL);
                bool bad1 = (c1 > ri0) || (q0 + c1 >= LL);
                bool bad2 = (c0 > ri1) || (q0 + c0 >= LL);
                bool bad3 = (c1 > ri1) || (q0 + c1 >= LL);
                if (bad0) s[nt][0] = -1e30f;
                if (bad1) s[nt][1] = -1e30f;
                if (bad2) s[nt][2] = -1e30f;
                if (bad3) s[nt][3] = -1e30f;
            }
        }

        // Online softmax (register, quad shfl reductions)
        float mx0 = m0, mx1 = m1;
        #pragma unroll
        for (int nt = 0; nt < 8; nt++) {
            mx0 = fmaxf(mx0, fmaxf(s[nt][0], s[nt][1]));
            mx1 = fmaxf(mx1, fmaxf(s[nt][2], s[nt][3]));
        }
        mx0 = fmaxf(mx0, __shfl_xor_sync(0xffffffff, mx0, 1));
        mx0 = fmaxf(mx0, __shfl_xor_sync(0xffffffff, mx0, 2));
        mx1 = fmaxf(mx1, __shfl_xor_sync(0xffffffff, mx1, 1));
        mx1 = fmaxf(mx1, __shfl_xor_sync(0xffffffff, mx1, 2));

        float a0 = __expf(m0 - mx0);
        float a1 = __expf(m1 - mx1);
        float sum0 = 0.f, sum1 = 0.f;
        #pragma unroll
        for (int nt = 0; nt < 8; nt++) {
            s[nt][0] = __expf(s[nt][0] - mx0);
            s[nt][1] = __expf(s[nt][1] - mx0);
            s[nt][2] = __expf(s[nt][2] - mx1);
            s[nt][3] = __expf(s[nt][3] - mx1);
            sum0 += s[nt][0] + s[nt][1];
            sum1 += s[nt][2] + s[nt][3];
        }
        sum0 += __shfl_xor_sync(0xffffffff, sum0, 1);
        sum0 += __shfl_xor_sync(0xffffffff, sum0, 2);
        sum1 += __shfl_xor_sync(0xffffffff, sum1, 1);
        sum1 += __shfl_xor_sync(0xffffffff, sum1, 2);

        m0 = mx0; m1 = mx1;
        l0 = l0 * a0 + sum0;
        l1 = l1 * a1 + sum1;

        #pragma unroll
        for (int nt = 0; nt < 8; nt++) {
            o[nt][0] *= a0; o[nt][1] *= a0;
            o[nt][2] *= a1; o[nt][3] *= a1;
        }

        // Stage P (each warp writes only its own 16 rows)
        #pragma unroll
        for (int nt = 0; nt < 8; nt++) {
            int c = nt * 8 + 2 * (lane & 3);
            *(float2*)(ps + (r0)     * AT_SMS + c) = make_float2(s[nt][0], s[nt][1]);
            *(float2*)(ps + (r0 + 8) * AT_SMS + c) = make_float2(s[nt][2], s[nt][3]);
        }
        __syncwarp();

        // O += P V
        #pragma unroll
        for (int kc = 0; kc < 8; kc++) {
            unsigned pa[4];
            int c0 = kc * 8 + (lane & 3);
            pa[0] = f2tf32(ps[(r0)     * AT_SMS + c0]);
            pa[1] = f2tf32(ps[(r0 + 8) * AT_SMS + c0]);
            pa[2] = f2tf32(ps[(r0)     * AT_SMS + c0 + 4]);
            pa[3] = f2tf32(ps[(r0 + 8) * AT_SMS + c0 + 4]);
            #pragma unroll
            for (int nt = 0; nt < 8; nt++) {
                int n0 = nt * 8 + (lane >> 2);
                unsigned bf[2];
                bf[0] = f2tf32(V[(kc * 8 + (lane & 3))     * AT_SMS + n0]);
                bf[1] = f2tf32(V[(kc * 8 + (lane & 3) + 4) * AT_SMS + n0]);
                mma_tf32(o[nt], pa, bf);
            }
        }
    }

    // Epilogue: normalize, store
    float inv0 = 1.0f / l0;
    float inv1 = 1.0f / l1;
    int row0 = q0 + r0;
    int row1 = row0 + 8;
    #pragma unroll
    for (int nt = 0; nt < 8; nt++) {
        int col = h * HDIM + nt * 8 + 2 * (lane & 3);
        if (row0 < LL) {
            float2 w = make_float2(o[nt][0] * inv0, o[nt][1] * inv0);
            *(float2*)(att + (size_t)(b * LL + row0) * DD + col) = w;
        }
        if (row1 < LL) {
            float2 w = make_float2(o[nt][2] * inv1, o[nt][3] * inv1);
            *(float2*)(att + (size_t)(b * LL + row1) * DD + col) = w;
        }
    }
}

// ---------------------------------------------------------------------------
extern "C" void kernel_launch(void* const* d_in, const int* in_sizes, int n_in,
                              void* d_out, int out_size)
{
    const float* x    = (const float*)d_in[0];
    const float* Wqkv = (const float*)d_in[1];
    const float* bqkv = (const float*)d_in[2];
    const float* Wo   = (const float*)d_in[3];
    const float* bo   = (const float*)d_in[4];
    float* out = (float*)d_out;

    float* qkv; cudaGetSymbolAddress((void**)&qkv, g_qkv);
    float* att; cudaGetSymbolAddress((void**)&att, g_att);

    const int gemm_smem = 2 * (ASZ + BSZ) * (int)sizeof(float);
    cudaFuncSetAttribute(gemm_tf32_bias_kernel,
                         cudaFuncAttributeMaxDynamicSharedMemorySize, gemm_smem);
    cudaFuncSetAttribute(attn_mma_kernel,
                         cudaFuncAttributeMaxDynamicSharedMemorySize, ATTN_SMEM_BYTES);

    const int gridM = (MTOT + TBM - 1) / TBM;  // 63

    gemm_tf32_bias_kernel<<<dim3(3 * DD / TBN, gridM), 256, gemm_smem>>>(
        x, Wqkv, bqkv, qkv, MTOT, 3 * DD, DD);

    attn_mma_kernel<<<dim3(16, BB * HH), 128, ATTN_SMEM_BYTES>>>(qkv, att);

    gemm_tf32_bias_kernel<<<dim3(DD / TBN, gridM), 256, gemm_smem>>>(
        att, Wo, bo, out, MTOT, DD, DD);
}

// round 4
// speedup vs baseline: 9.2384x; 2.0127x over previous
#include <cuda_runtime.h>
#include <cuda_fp16.h>
#include <math.h>

#define BB 8
#define LL 1000
#define DD 1024
#define HH 16
#define HDIM 64
#define MTOT (BB * LL)   // 8000

// Scratch (__device__ globals; allocation-free rule)
__device__ __align__(16) __half g_xh[(size_t)MTOT * DD];
__device__ __align__(16) __half g_wqkvh[(size_t)DD * 3 * DD];
__device__ __align__(16) __half g_woh[(size_t)DD * DD];
__device__ __align__(16) __half g_qkvh[(size_t)MTOT * 3 * DD];
__device__ __align__(16) __half g_atth[(size_t)MTOT * DD];

// ---------------------------------------------------------------------------
// helpers
// ---------------------------------------------------------------------------
__device__ __forceinline__ void mma_f16(float* c, const unsigned* a, const unsigned* b) {
    asm volatile(
        "mma.sync.aligned.m16n8k16.row.col.f32.f16.f16.f32 "
        "{%0,%1,%2,%3},{%4,%5,%6,%7},{%8,%9},{%0,%1,%2,%3};"
        : "+f"(c[0]), "+f"(c[1]), "+f"(c[2]), "+f"(c[3])
        : "r"(a[0]), "r"(a[1]), "r"(a[2]), "r"(a[3]), "r"(b[0]), "r"(b[1]));
}

__device__ __forceinline__ void ldsm_x4(unsigned& r0, unsigned& r1,
                                        unsigned& r2, unsigned& r3, const void* p) {
    unsigned addr = (unsigned)__cvta_generic_to_shared(p);
    asm volatile("ldmatrix.sync.aligned.m8n8.x4.shared.b16 {%0,%1,%2,%3}, [%4];"
                 : "=r"(r0), "=r"(r1), "=r"(r2), "=r"(r3) : "r"(addr));
}
__device__ __forceinline__ void ldsm_x4_t(unsigned& r0, unsigned& r1,
                                          unsigned& r2, unsigned& r3, const void* p) {
    unsigned addr = (unsigned)__cvta_generic_to_shared(p);
    asm volatile("ldmatrix.sync.aligned.m8n8.x4.trans.shared.b16 {%0,%1,%2,%3}, [%4];"
                 : "=r"(r0), "=r"(r1), "=r"(r2), "=r"(r3) : "r"(addr));
}

__device__ __forceinline__ void cp_async16(void* smem_dst, const void* gsrc, bool pred) {
    unsigned saddr = (unsigned)__cvta_generic_to_shared(smem_dst);
    int sz = pred ? 16 : 0;
    asm volatile("cp.async.cg.shared.global [%0], [%1], 16, %2;\n"
                 :: "r"(saddr), "l"(gsrc), "r"(sz));
}
__device__ __forceinline__ void cp_commit() { asm volatile("cp.async.commit_group;\n" ::); }
template <int N>
__device__ __forceinline__ void cp_wait() { asm volatile("cp.async.wait_group %0;\n" :: "n"(N)); }

__device__ __forceinline__ unsigned h2u(__half2 h) {
    return *(unsigned*)&h;
}

// ---------------------------------------------------------------------------
// fp32 -> fp16 conversion (4 elems/thread)
// ---------------------------------------------------------------------------
__global__ void f32_to_f16_kernel(const float* __restrict__ src,
                                  __half* __restrict__ dst, int n)
{
    int i = (blockIdx.x * blockDim.x + threadIdx.x) * 4;
    if (i < n) {
        float4 v = *(const float4*)(src + i);
        *(__half2*)(dst + i)     = __floats2half2_rn(v.x, v.y);
        *(__half2*)(dst + i + 2) = __floats2half2_rn(v.z, v.w);
    }
}

// ---------------------------------------------------------------------------
// FP16 tensor-core GEMM: C = A*B + bias. 128x128x32, 256 thr, 8 warps (64x32).
// ---------------------------------------------------------------------------
#define TBM 128
#define TBN 128
#define TBK 32
#define ASTR 40
#define BSTR 136
#define ASZH (TBM * ASTR)
#define BSZH (TBK * BSTR)
#define GEMM_SMEM_BYTES (2 * (ASZH + BSZH) * 2)

template <bool OUT_HALF>
__global__ __launch_bounds__(256, 2) void gemm_f16_kernel(
    const __half* __restrict__ A, const __half* __restrict__ Bm,
    const float* __restrict__ bias, void* __restrict__ Cout,
    int M, int N, int K)
{
    extern __shared__ __align__(16) char smem_raw[];
    __half* As = (__half*)smem_raw;
    __half* Bs = As + 2 * ASZH;

    const int tid = threadIdx.x;
    const int lane = tid & 31;
    const int warp = tid >> 5;
    const int wm = (warp & 1) * 64;
    const int wn = (warp >> 1) * 32;
    const int bm = blockIdx.y * TBM;
    const int bn = blockIdx.x * TBN;

    float acc[4][4][4];
    #pragma unroll
    for (int i = 0; i < 4; i++)
        #pragma unroll
        for (int j = 0; j < 4; j++)
            #pragma unroll
            for (int r = 0; r < 4; r++) acc[i][j][r] = 0.f;

    const int nT = K / TBK;

    {
        #pragma unroll
        for (int i = 0; i < 2; i++) {
            int chunk = tid + i * 256;
            int row = chunk >> 2, c8 = (chunk & 3) * 8;
            bool ok = (bm + row) < M;
            cp_async16(As + row * ASTR + c8, A + (size_t)(bm + row) * K + c8, ok);
        }
        #pragma unroll
        for (int i = 0; i < 2; i++) {
            int chunk = tid + i * 256;
            int row = chunk >> 4, c8 = (chunk & 15) * 8;
            cp_async16(Bs + row * BSTR + c8, Bm + (size_t)row * N + bn + c8, true);
        }
        cp_commit();
    }

    for (int t = 0; t < nT; t++) {
        int cur = t & 1;
        int nxt = cur ^ 1;
        if (t + 1 < nT) {
            int k0 = (t + 1) * TBK;
            #pragma unroll
            for (int i = 0; i < 2; i++) {
                int chunk = tid + i * 256;
                int row = chunk >> 2, c8 = (chunk & 3) * 8;
                bool ok = (bm + row) < M;
                cp_async16(As + nxt * ASZH + row * ASTR + c8,
                           A + (size_t)(bm + row) * K + k0 + c8, ok);
            }
            #pragma unroll
            for (int i = 0; i < 2; i++) {
                int chunk = tid + i * 256;
                int row = chunk >> 4, c8 = (chunk & 15) * 8;
                cp_async16(Bs + nxt * BSZH + row * BSTR + c8,
                           Bm + (size_t)(k0 + row) * N + bn + c8, true);
            }
            cp_commit();
            cp_wait<1>();
        } else {
            cp_wait<0>();
        }
        __syncthreads();

        const __half* Ab = As + cur * ASZH;
        const __half* Bb = Bs + cur * BSZH;

        #pragma unroll
        for (int ks = 0; ks < 2; ks++) {
            int k = ks * 16;
            unsigned afr[4][4], bfr[4][2];
            #pragma unroll
            for (int mt = 0; mt < 4; mt++) {
                const __half* p = Ab + (size_t)(wm + mt * 16 + (lane & 15)) * ASTR
                                  + k + ((lane >> 4) << 3);
                ldsm_x4(afr[mt][0], afr[mt][1], afr[mt][2], afr[mt][3], p);
            }
            #pragma unroll
            for (int np = 0; np < 2; np++) {
                const __half* p = Bb + (size_t)(k + (lane & 15)) * BSTR
                                  + wn + np * 16 + ((lane >> 4) << 3);
                ldsm_x4_t(bfr[2 * np][0], bfr[2 * np][1],
                          bfr[2 * np + 1][0], bfr[2 * np + 1][1], p);
            }
            #pragma unroll
            for (int mt = 0; mt < 4; mt++)
                #pragma unroll
                for (int nt = 0; nt < 4; nt++)
                    mma_f16(acc[mt][nt], afr[mt], bfr[nt]);
        }
        __syncthreads();
    }

    #pragma unroll
    for (int mt = 0; mt < 4; mt++) {
        int r_lo = bm + wm + mt * 16 + (lane >> 2);
        int r_hi = r_lo + 8;
        #pragma unroll
        for (int nt = 0; nt < 4; nt++) {
            int col = bn + wn + nt * 8 + (lane & 3) * 2;
            float b0 = bias[col], b1 = bias[col + 1];
            if (OUT_HALF) {
                __half* C = (__half*)Cout;
                if (r_lo < M)
                    *(__half2*)(C + (size_t)r_lo * N + col) =
                        __floats2half2_rn(acc[mt][nt][0] + b0, acc[mt][nt][1] + b1);
                if (r_hi < M)
                    *(__half2*)(C + (size_t)r_hi * N + col) =
                        __floats2half2_rn(acc[mt][nt][2] + b0, acc[mt][nt][3] + b1);
            } else {
                float* C = (float*)Cout;
                if (r_lo < M)
                    *(float2*)(C + (size_t)r_lo * N + col) =
                        make_float2(acc[mt][nt][0] + b0, acc[mt][nt][1] + b1);
                if (r_hi < M)
                    *(float2*)(C + (size_t)r_hi * N + col) =
                        make_float2(acc[mt][nt][2] + b0, acc[mt][nt][3] + b1);
            }
        }
    }
}

// ---------------------------------------------------------------------------
// FP16 flash attention (causal). 128 thr = 4 warps; warp owns 16 Q-rows of 64.
// ---------------------------------------------------------------------------
#define QSTR 72
#define AT_TILEH (64 * QSTR)
#define ATTN_SMEM_BYTES (5 * AT_TILEH * 2)   // 46080

__device__ __forceinline__ void attn_issue_kv(
    __half* kdst, __half* vdst, const __half* kptr, const __half* vptr,
    int j, int tid)
{
    #pragma unroll
    for (int i = 0; i < 4; i++) {
        int chunk = tid + i * 128;
        int r = chunk >> 3;
        int c = (chunk & 7) * 8;
        int kv = j * 64 + r;
        if (kv >= LL) kv = LL - 1;   // clamped; masked in S
        cp_async16(kdst + r * QSTR + c, kptr + (size_t)kv * (3 * DD) + c, true);
        cp_async16(vdst + r * QSTR + c, vptr + (size_t)kv * (3 * DD) + c, true);
    }
}

__global__ __launch_bounds__(128) void attn_f16_kernel(
    const __half* __restrict__ qkv, __half* __restrict__ att)
{
    extern __shared__ __align__(16) char smem_raw[];
    __half* qs = (__half*)smem_raw;
    __half* ks = qs + AT_TILEH;
    __half* vs = ks + 2 * AT_TILEH;

    const int tid = threadIdx.x;
    const int lane = tid & 31;
    const int warp = tid >> 5;
    const int qtile = 15 - blockIdx.x;
    const int bh = blockIdx.y;
    const int b = bh >> 4;
    const int h = bh & 15;
    const int q0 = qtile * 64;

    const size_t base = (size_t)b * LL * (3 * DD);
    const __half* qptr = qkv + base + h * HDIM;
    const __half* kptr = qkv + base + DD + h * HDIM;
    const __half* vptr = qkv + base + 2 * DD + h * HDIM;

    attn_issue_kv(ks, vs, kptr, vptr, 0, tid);
    #pragma unroll
    for (int i = 0; i < 4; i++) {
        int chunk = tid + i * 128;
        int r = chunk >> 3;
        int c = (chunk & 7) * 8;
        int qr = q0 + r;
        if (qr >= LL) qr = LL - 1;
        cp_async16(qs + r * QSTR + c, qptr + (size_t)qr * (3 * DD) + c, true);
    }
    cp_commit();
    cp_wait<0>();
    __syncthreads();

    unsigned qa[4][4];
    #pragma unroll
    for (int kc = 0; kc < 4; kc++) {
        const __half* p = qs + (size_t)(warp * 16 + (lane & 15)) * QSTR
                          + kc * 16 + ((lane >> 4) << 3);
        ldsm_x4(qa[kc][0], qa[kc][1], qa[kc][2], qa[kc][3], p);
    }

    float o[8][4];
    #pragma unroll
    for (int nt = 0; nt < 8; nt++)
        #pragma unroll
        for (int r = 0; r < 4; r++) o[nt][r] = 0.f;
    float m0 = -1e30f, m1 = -1e30f, l0 = 0.f, l1 = 0.f;

    for (int j = 0; j <= qtile; j++) {
        int cur = j & 1;
        int nxt = cur ^ 1;
        if (j > 0) { cp_wait<0>(); __syncthreads(); }

        if (j < qtile) {
            attn_issue_kv(ks + nxt * AT_TILEH, vs + nxt * AT_TILEH,
                          kptr, vptr, j + 1, tid);
            cp_commit();
        }

        const __half* K = ks + cur * AT_TILEH;
        const __half* V = vs + cur * AT_TILEH;

        float s[8][4];
        #pragma unroll
        for (int nt = 0; nt < 8; nt++)
            #pragma unroll
            for (int r = 0; r < 4; r++) s[nt][r] = 0.f;

        #pragma unroll
        for (int kc = 0; kc < 4; kc++) {
            #pragma unroll
            for (int np = 0; np < 4; np++) {
                unsigned b0[2], b1[2];
                const __half* p = K + (size_t)(np * 16 + (lane & 7) + ((lane >> 1) & 8)) * QSTR
                                  + kc * 16 + (lane & 8);
                ldsm_x4(b0[0], b0[1], b1[0], b1[1], p);
                mma_f16(s[2 * np],     qa[kc], b0);
                mma_f16(s[2 * np + 1], qa[kc], b1);
            }
        }

        #pragma unroll
        for (int nt = 0; nt < 8; nt++) {
            s[nt][0] *= 0.125f; s[nt][1] *= 0.125f;
            s[nt][2] *= 0.125f; s[nt][3] *= 0.125f;
        }

        if (j == qtile) {
            int row_g0 = q0 + warp * 16 + (lane >> 2);
            int row_g1 = row_g0 + 8;
            #pragma unroll
            for (int nt = 0; nt < 8; nt++) {
                int c0 = q0 + nt * 8 + 2 * (lane & 3);
                int c1 = c0 + 1;
                if (c0 > row_g0 || c0 >= LL) s[nt][0] = -1e30f;
                if (c1 > row_g0 || c1 >= LL) s[nt][1] = -1e30f;
                if (c0 > row_g1 || c0 >= LL) s[nt][2] = -1e30f;
                if (c1 > row_g1 || c1 >= LL) s[nt][3] = -1e30f;
            }
        }

        float mx0 = m0, mx1 = m1;
        #pragma unroll
        for (int nt = 0; nt < 8; nt++) {
            mx0 = fmaxf(mx0, fmaxf(s[nt][0], s[nt][1]));
            mx1 = fmaxf(mx1, fmaxf(s[nt][2], s[nt][3]));
        }
        mx0 = fmaxf(mx0, __shfl_xor_sync(0xffffffff, mx0, 1));
        mx0 = fmaxf(mx0, __shfl_xor_sync(0xffffffff, mx0, 2));
        mx1 = fmaxf(mx1, __shfl_xor_sync(0xffffffff, mx1, 1));
        mx1 = fmaxf(mx1, __shfl_xor_sync(0xffffffff, mx1, 2));

        float a0 = __expf(m0 - mx0);
        float a1 = __expf(m1 - mx1);
        float sum0 = 0.f, sum1 = 0.f;
        #pragma unroll
        for (int nt = 0; nt < 8; nt++) {
            s[nt][0] = __expf(s[nt][0] - mx0);
            s[nt][1] = __expf(s[nt][1] - mx0);
            s[nt][2] = __expf(s[nt][2] - mx1);
            s[nt][3] = __expf(s[nt][3] - mx1);
            sum0 += s[nt][0] + s[nt][1];
            sum1 += s[nt][2] + s[nt][3];
        }
        sum0 += __shfl_xor_sync(0xffffffff, sum0, 1);
        sum0 += __shfl_xor_sync(0xffffffff, sum0, 2);
        sum1 += __shfl_xor_sync(0xffffffff, sum1, 1);
        sum1 += __shfl_xor_sync(0xffffffff, sum1, 2);

        m0 = mx0; m1 = mx1;
        l0 = l0 * a0 + sum0;
        l1 = l1 * a1 + sum1;

        #pragma unroll
        for (int nt = 0; nt < 8; nt++) {
            o[nt][0] *= a0; o[nt][1] *= a0;
            o[nt][2] *= a1; o[nt][3] *= a1;
        }

        // P: c-frag -> a-frag in registers (no smem roundtrip)
        unsigned pa[4][4];
        #pragma unroll
        for (int kc = 0; kc < 4; kc++) {
            pa[kc][0] = h2u(__floats2half2_rn(s[2 * kc][0],     s[2 * kc][1]));
            pa[kc][1] = h2u(__floats2half2_rn(s[2 * kc][2],     s[2 * kc][3]));
            pa[kc][2] = h2u(__floats2half2_rn(s[2 * kc + 1][0], s[2 * kc + 1][1]));
            pa[kc][3] = h2u(__floats2half2_rn(s[2 * kc + 1][2], s[2 * kc + 1][3]));
        }

        #pragma unroll
        for (int kc = 0; kc < 4; kc++) {
            #pragma unroll
            for (int np = 0; np < 4; np++) {
                unsigned b0[2], b1[2];
                const __half* p = V + (size_t)(kc * 16 + (lane & 15)) * QSTR
                                  + np * 16 + ((lane >> 4) << 3);
                ldsm_x4_t(b0[0], b0[1], b1[0], b1[1], p);
                mma_f16(o[2 * np],     pa[kc], b0);
                mma_f16(o[2 * np + 1], pa[kc], b1);
            }
        }
    }

    float inv0 = 1.0f / l0;
    float inv1 = 1.0f / l1;
    int row0 = q0 + warp * 16 + (lane >> 2);
    int row1 = row0 + 8;
    #pragma unroll
    for (int nt = 0; nt < 8; nt++) {
        int col = h * HDIM + nt * 8 + 2 * (lane & 3);
        if (row0 < LL)
            *(__half2*)(att + (size_t)(b * LL + row0) * DD + col) =
                __floats2half2_rn(o[nt][0] * inv0, o[nt][1] * inv0);
        if (row1 < LL)
            *(__half2*)(att + (size_t)(b * LL + row1) * DD + col) =
                __floats2half2_rn(o[nt][2] * inv1, o[nt][3] * inv1);
    }
}

// ---------------------------------------------------------------------------
extern "C" void kernel_launch(void* const* d_in, const int* in_sizes, int n_in,
                              void* d_out, int out_size)
{
    const float* x    = (const float*)d_in[0];
    const float* Wqkv = (const float*)d_in[1];
    const float* bqkv = (const float*)d_in[2];
    const float* Wo   = (const float*)d_in[3];
    const float* bo   = (const float*)d_in[4];
    float* out = (float*)d_out;

    __half *xh, *wqkvh, *woh, *qkvh, *atth;
    cudaGetSymbolAddress((void**)&xh, g_xh);
    cudaGetSymbolAddress((void**)&wqkvh, g_wqkvh);
    cudaGetSymbolAddress((void**)&woh, g_woh);
    cudaGetSymbolAddress((void**)&qkvh, g_qkvh);
    cudaGetSymbolAddress((void**)&atth, g_atth);

    cudaFuncSetAttribute(gemm_f16_kernel<true>,
                         cudaFuncAttributeMaxDynamicSharedMemorySize, GEMM_SMEM_BYTES);
    cudaFuncSetAttribute(gemm_f16_kernel<false>,
                         cudaFuncAttributeMaxDynamicSharedMemorySize, GEMM_SMEM_BYTES);
    cudaFuncSetAttribute(attn_f16_kernel,
                         cudaFuncAttributeMaxDynamicSharedMemorySize, ATTN_SMEM_BYTES);

    int n1 = MTOT * DD;
    int n2 = DD * 3 * DD;
    int n3 = DD * DD;
    f32_to_f16_kernel<<<n1 / 1024, 256>>>(x, xh, n1);
    f32_to_f16_kernel<<<n2 / 1024, 256>>>(Wqkv, wqkvh, n2);
    f32_to_f16_kernel<<<n3 / 1024, 256>>>(Wo, woh, n3);

    const int gridM = (MTOT + TBM - 1) / TBM;  // 63

    gemm_f16_kernel<true><<<dim3(3 * DD / TBN, gridM), 256, GEMM_SMEM_BYTES>>>(
        xh, wqkvh, bqkv, qkvh, MTOT, 3 * DD, DD);

    attn_f16_kernel<<<dim3(16, BB * HH), 128, ATTN_SMEM_BYTES>>>(qkvh, atth);

    gemm_f16_kernel<false><<<dim3(DD / TBN, gridM), 256, GEMM_SMEM_BYTES>>>(
        atth, woh, bo, out, MTOT, DD, DD);
}